// round 1
// baseline (speedup 1.0000x reference)
#include <cuda_runtime.h>

// Fused: z = fq(conv1d(fq(conv1d(fq(x), fq(w1*sf)) + fq(bfold)), fq(w2)) + fq(b2))
// x: [16,4,L] f32, out z: [16,2,L] f32, L = 524288.

#define TL 2048      // tile positions per block
#define NT 256       // threads per block

__device__ __forceinline__ float fq8(float v) {
    // clip(floor(v*128 + 0.5), -128, 127) / 128
    float q = floorf(fmaf(v, 128.0f, 0.5f));
    q = fminf(fmaxf(q, -128.0f), 127.0f);
    return q * 0.0078125f;
}

__global__ __launch_bounds__(NT) void fused_qconv_kernel(
    const float* __restrict__ x,
    const float* __restrict__ w1, const float* __restrict__ b1,
    const float* __restrict__ gamma, const float* __restrict__ beta,
    const float* __restrict__ bn_mean, const float* __restrict__ bn_var,
    const float* __restrict__ w2, const float* __restrict__ b2,
    float* __restrict__ out, int L)
{
    __shared__ float wq1s[8][4][3];
    __shared__ float bq1s[8];
    __shared__ float wq2s[2][8][3];
    __shared__ float bq2s[2];
    extern __shared__ float smem[];
    float* xs = smem;                      // [4][TL+4]  fq(x) with halo 2
    float* ys = smem + 4 * (TL + 4);       // [8][TL+2]  fq(y) with halo 1

    const int tid = threadIdx.x;
    const int b   = blockIdx.y;
    const int tile_start = blockIdx.x * TL;

    // ---- fold + fake-quant the tiny weight set (154 values) ----
    if (tid < 96) {
        int o = tid / 12;
        double sf = (double)gamma[o] / sqrt((double)bn_var[o] + 1e-5);
        ((float*)wq1s)[tid] = fq8(w1[tid] * (float)sf);
    } else if (tid < 104) {
        int o = tid - 96;
        double sf = (double)gamma[o] / sqrt((double)bn_var[o] + 1e-5);
        bq1s[o] = fq8((b1[o] - bn_mean[o]) * (float)sf + beta[o]);
    } else if (tid < 152) {
        ((float*)wq2s)[tid - 104] = fq8(w2[tid - 104]);
    } else if (tid < 154) {
        bq2s[tid - 152] = fq8(b2[tid - 152]);
    }

    // ---- stage 1: load + fq x tile (4 channels, halo of 2 each side) ----
    const float* xb = x + (size_t)b * 4 * L;
    #pragma unroll 4
    for (int idx = tid; idx < 4 * (TL + 4); idx += NT) {
        int c = idx / (TL + 4);
        int j = idx - c * (TL + 4);
        int gp = tile_start - 2 + j;
        float v = (gp >= 0 && gp < L) ? xb[(size_t)c * L + gp] : 0.0f;
        xs[idx] = fq8(v);
    }
    __syncthreads();

    // ---- stage 2: y = fq(conv1(xq) + bq1), computed once per position ----
    // y position q = tile_start - 1 + j needs xs[c][j .. j+2]
    for (int j = tid; j < TL + 2; j += NT) {
        int q = tile_start - 1 + j;
        float xv[4][3];
        #pragma unroll
        for (int c = 0; c < 4; c++)
            #pragma unroll
            for (int k = 0; k < 3; k++)
                xv[c][k] = xs[c * (TL + 4) + j + k];
        bool valid = (q >= 0 && q < L);
        #pragma unroll
        for (int oc = 0; oc < 8; oc++) {
            float acc = bq1s[oc];
            #pragma unroll
            for (int c = 0; c < 4; c++)
                #pragma unroll
                for (int k = 0; k < 3; k++)
                    acc = fmaf(xv[c][k], wq1s[oc][c][k], acc);
            ys[oc * (TL + 2) + j] = valid ? fq8(acc) : 0.0f;  // zero = conv2's pad
        }
    }
    __syncthreads();

    // ---- stage 3: z = fq(conv2(y) + bq2), coalesced store ----
    float* ob = out + (size_t)b * 2 * L;
    for (int j = tid; j < TL; j += NT) {
        int l = tile_start + j;
        if (l >= L) break;
        float a0 = bq2s[0], a1 = bq2s[1];
        #pragma unroll
        for (int oc = 0; oc < 8; oc++) {
            float y0 = ys[oc * (TL + 2) + j];
            float y1 = ys[oc * (TL + 2) + j + 1];
            float y2 = ys[oc * (TL + 2) + j + 2];
            a0 = fmaf(y0, wq2s[0][oc][0], a0);
            a0 = fmaf(y1, wq2s[0][oc][1], a0);
            a0 = fmaf(y2, wq2s[0][oc][2], a0);
            a1 = fmaf(y0, wq2s[1][oc][0], a1);
            a1 = fmaf(y1, wq2s[1][oc][1], a1);
            a1 = fmaf(y2, wq2s[1][oc][2], a1);
        }
        ob[l]     = fq8(a0);
        ob[L + l] = fq8(a1);
    }
}

extern "C" void kernel_launch(void* const* d_in, const int* in_sizes, int n_in,
                              void* d_out, int out_size)
{
    const float* x       = (const float*)d_in[0];
    const float* w1      = (const float*)d_in[1];
    const float* b1      = (const float*)d_in[2];
    const float* gamma   = (const float*)d_in[3];
    const float* beta    = (const float*)d_in[4];
    const float* bn_mean = (const float*)d_in[5];
    const float* bn_var  = (const float*)d_in[6];
    const float* w2      = (const float*)d_in[7];
    const float* b2      = (const float*)d_in[8];
    float* out = (float*)d_out;

    const int B = 16;
    const int L = in_sizes[0] / (B * 4);

    const int smem_bytes = (4 * (TL + 4) + 8 * (TL + 2)) * (int)sizeof(float);
    cudaFuncSetAttribute(fused_qconv_kernel,
                         cudaFuncAttributeMaxDynamicSharedMemorySize, smem_bytes);

    dim3 grid((L + TL - 1) / TL, B);
    fused_qconv_kernel<<<grid, NT, smem_bytes>>>(
        x, w1, b1, gamma, beta, bn_mean, bn_var, w2, b2, out, L);
}

// round 2
// speedup vs baseline: 2.7925x; 2.7925x over previous
#include <cuda_runtime.h>

// Fully integer-exact fused QAT conv stack:
//   z = fq(conv1d(fq(conv1d(fq(x), fq(w1*sf)) + fq(bfold)), fq(w2)) + fq(b2))
// All fq outputs are int8/128, convs done with DP4A, requant = (+64)>>7, clamp.
// Bit-exact vs the fp32 reference (reference sums stay < 2^24 -> exact).

#define TL 2048      // tile positions per block
#define NT 256       // threads per block

__device__ __forceinline__ int q8i(float v) {
    // round-half-up to int with clip [-128,127]
    int i = __float2int_rd(fmaf(v, 128.0f, 0.5f));   // floor(v*128 + 0.5)
    return min(max(i, -128), 127);
}

__device__ __forceinline__ int pk4(int a, int b, int c, int d) {
    unsigned p = __byte_perm((unsigned)a, (unsigned)b, 0x0040); // [a0,b0,-,-]
    p = __byte_perm(p, (unsigned)c, 0x0410);                     // [a0,b0,c0,-]
    return (int)__byte_perm(p, (unsigned)d, 0x4210);             // [a0,b0,c0,d0]
}

__global__ __launch_bounds__(NT) void fused_qconv_i8(
    const float* __restrict__ x,
    const float* __restrict__ w1, const float* __restrict__ b1,
    const float* __restrict__ gamma, const float* __restrict__ beta,
    const float* __restrict__ bn_mean, const float* __restrict__ bn_var,
    const float* __restrict__ w2, const float* __restrict__ b2,
    float* __restrict__ out, int L)
{
    __shared__ int w1p[8][3];        // conv1 weights: 4 in-ch packed per (oc,k)
    __shared__ int bo1[8];           // 128*b1_int + 64
    __shared__ int w2p[2][3][2];     // conv2 weights: [oc2][k][half], 4 ch per word
    __shared__ int bo2[2];           // 128*b2_int + 64
    extern __shared__ int smem[];
    int*  xs = smem;                       // [TL+4] packed fq(x), halo 2
    int2* ys = (int2*)(smem + (TL + 4));   // [TL+2] packed fq(y), halo 1

    const int tid = threadIdx.x;
    const int bb  = blockIdx.y;
    const int ts  = blockIdx.x * TL;

    // ---- quantize + pack the tiny weight set ----
    if (tid < 24) {                                   // w1: oc in [0,8), k in [0,3)
        int oc = tid / 3, k = tid % 3;
        float sf = (float)((double)gamma[oc] / sqrt((double)bn_var[oc] + 1e-5));
        int q0 = q8i(w1[oc*12 + 0*3 + k] * sf);
        int q1 = q8i(w1[oc*12 + 1*3 + k] * sf);
        int q2 = q8i(w1[oc*12 + 2*3 + k] * sf);
        int q3 = q8i(w1[oc*12 + 3*3 + k] * sf);
        w1p[oc][k] = pk4(q0, q1, q2, q3);
    } else if (tid < 32) {                            // folded bias 1
        int oc = tid - 24;
        float sf = (float)((double)gamma[oc] / sqrt((double)bn_var[oc] + 1e-5));
        int bi = q8i((b1[oc] - bn_mean[oc]) * sf + beta[oc]);
        bo1[oc] = bi * 128 + 64;
    } else if (tid < 44) {                            // w2: 2 oc x 3 k x 2 halves
        int idx = tid - 32;
        int oc = idx / 6, r = idx % 6, k = r >> 1, h = r & 1;
        int q0 = q8i(w2[oc*24 + (h*4 + 0)*3 + k]);
        int q1 = q8i(w2[oc*24 + (h*4 + 1)*3 + k]);
        int q2 = q8i(w2[oc*24 + (h*4 + 2)*3 + k]);
        int q3 = q8i(w2[oc*24 + (h*4 + 3)*3 + k]);
        w2p[oc][k][h] = pk4(q0, q1, q2, q3);
    } else if (tid < 46) {                            // bias 2
        int oc = tid - 44;
        bo2[oc] = q8i(b2[oc]) * 128 + 64;
    }

    // ---- stage 1: load x, fake-quant to int8, pack 4 channels/word ----
    const float* xb = x + (size_t)bb * 4 * L;
    for (int j = tid; j < TL + 4; j += NT) {
        int gp = ts - 2 + j;
        int p = 0;
        if (gp >= 0 && gp < L) {
            int i0 = q8i(xb[gp]);
            int i1 = q8i(xb[(size_t)L + gp]);
            int i2 = q8i(xb[(size_t)2*L + gp]);
            int i3 = q8i(xb[(size_t)3*L + gp]);
            p = pk4(i0, i1, i2, i3);
        }
        xs[j] = p;
    }
    __syncthreads();

    // ---- stage 2: y = requant(conv1), packed int8 x8 channels ----
    for (int j = tid; j < TL + 2; j += NT) {
        int q  = ts - 1 + j;
        int x0 = xs[j], x1 = xs[j + 1], x2 = xs[j + 2];
        int yv[8];
        #pragma unroll
        for (int oc = 0; oc < 8; oc++) {
            int acc = __dp4a(x0, w1p[oc][0], bo1[oc]);
            acc     = __dp4a(x1, w1p[oc][1], acc);
            acc     = __dp4a(x2, w1p[oc][2], acc);
            yv[oc]  = min(max(acc >> 7, -128), 127);
        }
        bool valid = (q >= 0) && (q < L);
        int lo = pk4(yv[0], yv[1], yv[2], yv[3]);
        int hi = pk4(yv[4], yv[5], yv[6], yv[7]);
        ys[j] = valid ? make_int2(lo, hi) : make_int2(0, 0);
    }
    __syncthreads();

    // ---- stage 3: z = dequant(requant(conv2)), coalesced store ----
    float* ob = out + (size_t)bb * 2 * L;
    for (int j = tid; j < TL; j += NT) {
        int l = ts + j;
        if (l >= L) break;
        int2 y0 = ys[j], y1 = ys[j + 1], y2 = ys[j + 2];
        #pragma unroll
        for (int oc = 0; oc < 2; oc++) {
            int acc = __dp4a(y0.x, w2p[oc][0][0], bo2[oc]);
            acc     = __dp4a(y0.y, w2p[oc][0][1], acc);
            acc     = __dp4a(y1.x, w2p[oc][1][0], acc);
            acc     = __dp4a(y1.y, w2p[oc][1][1], acc);
            acc     = __dp4a(y2.x, w2p[oc][2][0], acc);
            acc     = __dp4a(y2.y, w2p[oc][2][1], acc);
            int zi  = min(max(acc >> 7, -128), 127);
            ob[(size_t)oc * L + l] = (float)zi * 0.0078125f;
        }
    }
}

extern "C" void kernel_launch(void* const* d_in, const int* in_sizes, int n_in,
                              void* d_out, int out_size)
{
    const float* x       = (const float*)d_in[0];
    const float* w1      = (const float*)d_in[1];
    const float* b1      = (const float*)d_in[2];
    const float* gamma   = (const float*)d_in[3];
    const float* beta    = (const float*)d_in[4];
    const float* bn_mean = (const float*)d_in[5];
    const float* bn_var  = (const float*)d_in[6];
    const float* w2      = (const float*)d_in[7];
    const float* b2      = (const float*)d_in[8];
    float* out = (float*)d_out;

    const int B = 16;
    const int L = in_sizes[0] / (B * 4);

    const int smem_bytes = ((TL + 4) + 2 * (TL + 2)) * (int)sizeof(int); // 24.6 KB

    dim3 grid((L + TL - 1) / TL, B);
    fused_qconv_i8<<<grid, NT, smem_bytes>>>(
        x, w1, b1, gamma, beta, bn_mean, bn_var, w2, b2, out, L);
}

// round 3
// speedup vs baseline: 3.4477x; 1.2346x over previous
#include <cuda_runtime.h>

// Integer-exact fused QAT conv stack (bit-exact vs fp32 reference):
//   z = fq(conv1d(fq(conv1d(fq(x), fq(w1*sf)) + fq(bfold)), fq(w2)) + fq(b2))
// fq outputs are int8/128; convs via DP4A; requant = (+64)>>7 with sat-pack.

#define TL 4096      // tile positions per block
#define NT 256       // threads per block

__device__ __forceinline__ int cvtrd(float v) {
    // floor(v*128 + 0.5) as int (clamp happens in sat-pack)
    return __float2int_rd(fmaf(v, 128.0f, 0.5f));
}

__device__ __forceinline__ int packsat2(int a, int b, int c) {
    int d;
    asm("cvt.pack.sat.s8.s32.b32 %0, %1, %2, %3;"
        : "=r"(d) : "r"(a), "r"(b), "r"(c));
    return d;
}
// Packs 4 ints (saturated to s8) into one word. Byte order is a fixed
// permutation of (v0..v3); weights and data use the SAME helper, so dp4a
// dot products are order-invariant.
__device__ __forceinline__ int pack4sat(int v0, int v1, int v2, int v3) {
    return packsat2(v1, v0, packsat2(v3, v2, 0));
}

__global__ __launch_bounds__(NT) void fused_qconv_i8v(
    const float* __restrict__ x,
    const float* __restrict__ w1, const float* __restrict__ b1,
    const float* __restrict__ gamma, const float* __restrict__ beta,
    const float* __restrict__ bn_mean, const float* __restrict__ bn_var,
    const float* __restrict__ w2, const float* __restrict__ b2,
    float* __restrict__ out, int L)
{
    __shared__ int w1p[8][3];        // conv1 w: 4 in-ch packed per (oc,k)
    __shared__ int bo1[8];           // 128*b1_int + 64
    __shared__ int w2p[2][3][2];     // conv2 w: [oc][k][half]
    __shared__ int bo2[2];           // 128*b2_int + 64
    extern __shared__ int smem[];
    int* xs  = smem;                 // [TL+8]  packed x, xs[i] = pos ts-4+i
    int* ysL = smem + (TL + 8);      // [TL+4]  y ch0..3, ysL[i] = pos ts-2+i
    int* ysH = ysL + (TL + 4);       // [TL+4]  y ch4..7

    const int tid = threadIdx.x;
    const int bb  = blockIdx.y;
    const int ts  = blockIdx.x * TL;
    const float* xb = x + (size_t)bb * 4 * L;

    // ---- halos + tiny weight set (disjoint tid ranges) ----
    if (tid < 4) {                                // left halo: pos ts-4+tid
        int p = ts - 4 + tid, w = 0;
        if (p >= 0)
            w = pack4sat(cvtrd(xb[p]), cvtrd(xb[(size_t)L + p]),
                         cvtrd(xb[(size_t)2*L + p]), cvtrd(xb[(size_t)3*L + p]));
        xs[tid] = w;
    } else if (tid < 8) {                         // right halo: pos ts+TL+(tid-4)
        int p = ts + TL + (tid - 4), w = 0;
        if (p < L)
            w = pack4sat(cvtrd(xb[p]), cvtrd(xb[(size_t)L + p]),
                         cvtrd(xb[(size_t)2*L + p]), cvtrd(xb[(size_t)3*L + p]));
        xs[TL + 4 + (tid - 4)] = w;
    } else if (tid >= 32 && tid < 56) {           // w1 packed
        int t = tid - 32, oc = t / 3, k = t % 3;
        float sf = (float)((double)gamma[oc] / sqrt((double)bn_var[oc] + 1e-5));
        const float* wb = w1 + oc * 12 + k;
        w1p[oc][k] = pack4sat(cvtrd(wb[0] * sf), cvtrd(wb[3] * sf),
                              cvtrd(wb[6] * sf), cvtrd(wb[9] * sf));
    } else if (tid >= 56 && tid < 64) {           // folded bias 1
        int oc = tid - 56;
        float sf = (float)((double)gamma[oc] / sqrt((double)bn_var[oc] + 1e-5));
        int bi = min(max(cvtrd((b1[oc] - bn_mean[oc]) * sf + beta[oc]), -128), 127);
        bo1[oc] = bi * 128 + 64;
    } else if (tid >= 64 && tid < 76) {           // w2 packed
        int t = tid - 64, oc = t / 6, r = t % 6, k = r >> 1, h = r & 1;
        const float* wb = w2 + oc * 24 + h * 12 + k;
        w2p[oc][k][h] = pack4sat(cvtrd(wb[0]), cvtrd(wb[3]),
                                 cvtrd(wb[6]), cvtrd(wb[9]));
    } else if (tid >= 76 && tid < 78) {           // bias 2
        int oc = tid - 76;
        bo2[oc] = min(max(cvtrd(b2[oc]), -128), 127) * 128 + 64;
    }

    // ---- stage 1: vectorized load + quantize + pack 4 ch/word ----
    for (int g = tid; g < TL / 4; g += NT) {
        int p = ts + 4 * g;
        float4 a = *(const float4*)(xb + p);
        float4 b = *(const float4*)(xb + (size_t)L + p);
        float4 c = *(const float4*)(xb + (size_t)2 * L + p);
        float4 d = *(const float4*)(xb + (size_t)3 * L + p);
        int4 w;
        w.x = pack4sat(cvtrd(a.x), cvtrd(b.x), cvtrd(c.x), cvtrd(d.x));
        w.y = pack4sat(cvtrd(a.y), cvtrd(b.y), cvtrd(c.y), cvtrd(d.y));
        w.z = pack4sat(cvtrd(a.z), cvtrd(b.z), cvtrd(c.z), cvtrd(d.z));
        w.w = pack4sat(cvtrd(a.w), cvtrd(b.w), cvtrd(c.w), cvtrd(d.w));
        *(int4*)(xs + 4 + 4 * g) = w;
    }
    __syncthreads();

    // ---- stage 2: y = satpack((conv1 + 128*b + 64) >> 7), 4 pos/thread ----
    for (int g = tid; g < (TL + 4) / 4; g += NT) {
        int m = 4 * g;
        int4 va = *(const int4*)(xs + m);
        int4 vb = *(const int4*)(xs + m + 4);
        int xv[8] = {va.x, va.y, va.z, va.w, vb.x, vb.y, vb.z, vb.w};
        int lo[4], hi[4];
        #pragma unroll
        for (int p = 0; p < 4; p++) {
            int x0 = xv[p + 1], x1 = xv[p + 2], x2 = xv[p + 3];
            int yv[8];
            #pragma unroll
            for (int oc = 0; oc < 8; oc++) {
                int acc = __dp4a(x0, w1p[oc][0], bo1[oc]);
                acc     = __dp4a(x1, w1p[oc][1], acc);
                acc     = __dp4a(x2, w1p[oc][2], acc);
                yv[oc]  = acc >> 7;
            }
            int q = ts - 2 + m + p;
            bool valid = (q >= 0) && (q < L);
            lo[p] = valid ? pack4sat(yv[0], yv[1], yv[2], yv[3]) : 0;
            hi[p] = valid ? pack4sat(yv[4], yv[5], yv[6], yv[7]) : 0;
        }
        *(int4*)(ysL + m) = make_int4(lo[0], lo[1], lo[2], lo[3]);
        *(int4*)(ysH + m) = make_int4(hi[0], hi[1], hi[2], hi[3]);
    }
    __syncthreads();

    // ---- stage 3: z = dequant(clamp((conv2 + 128*b + 64) >> 7)), 4 pos/thread ----
    float* ob = out + (size_t)bb * 2 * L;
    for (int g = tid; g < TL / 4; g += NT) {
        int j = 4 * g;
        int4 la = *(const int4*)(ysL + j);
        int4 lb = *(const int4*)(ysL + j + 4);
        int4 ha = *(const int4*)(ysH + j);
        int4 hb = *(const int4*)(ysH + j + 4);
        int YL[8] = {la.x, la.y, la.z, la.w, lb.x, lb.y, lb.z, lb.w};
        int YH[8] = {ha.x, ha.y, ha.z, ha.w, hb.x, hb.y, hb.z, hb.w};
        float f0[4], f1[4];
        #pragma unroll
        for (int p = 0; p < 4; p++) {
            int a0 = __dp4a(YL[p + 1], w2p[0][0][0], bo2[0]);
            a0     = __dp4a(YH[p + 1], w2p[0][0][1], a0);
            a0     = __dp4a(YL[p + 2], w2p[0][1][0], a0);
            a0     = __dp4a(YH[p + 2], w2p[0][1][1], a0);
            a0     = __dp4a(YL[p + 3], w2p[0][2][0], a0);
            a0     = __dp4a(YH[p + 3], w2p[0][2][1], a0);
            int a1 = __dp4a(YL[p + 1], w2p[1][0][0], bo2[1]);
            a1     = __dp4a(YH[p + 1], w2p[1][0][1], a1);
            a1     = __dp4a(YL[p + 2], w2p[1][1][0], a1);
            a1     = __dp4a(YH[p + 2], w2p[1][1][1], a1);
            a1     = __dp4a(YL[p + 3], w2p[1][2][0], a1);
            a1     = __dp4a(YH[p + 3], w2p[1][2][1], a1);
            f0[p] = (float)min(max(a0 >> 7, -128), 127) * 0.0078125f;
            f1[p] = (float)min(max(a1 >> 7, -128), 127) * 0.0078125f;
        }
        *(float4*)(ob + ts + j)     = make_float4(f0[0], f0[1], f0[2], f0[3]);
        *(float4*)(ob + L + ts + j) = make_float4(f1[0], f1[1], f1[2], f1[3]);
    }
}

extern "C" void kernel_launch(void* const* d_in, const int* in_sizes, int n_in,
                              void* d_out, int out_size)
{
    const float* x       = (const float*)d_in[0];
    const float* w1      = (const float*)d_in[1];
    const float* b1      = (const float*)d_in[2];
    const float* gamma   = (const float*)d_in[3];
    const float* beta    = (const float*)d_in[4];
    const float* bn_mean = (const float*)d_in[5];
    const float* bn_var  = (const float*)d_in[6];
    const float* w2      = (const float*)d_in[7];
    const float* b2      = (const float*)d_in[8];
    float* out = (float*)d_out;

    const int B = 16;
    const int L = in_sizes[0] / (B * 4);

    const int smem_bytes = ((TL + 8) + 2 * (TL + 4)) * (int)sizeof(int); // ~48 KB
    cudaFuncSetAttribute(fused_qconv_i8v,
                         cudaFuncAttributeMaxDynamicSharedMemorySize, smem_bytes);

    dim3 grid((L + TL - 1) / TL, B);
    fused_qconv_i8v<<<grid, NT, smem_bytes>>>(
        x, w1, b1, gamma, beta, bn_mean, bn_var, w2, b2, out, L);
}

// round 4
// speedup vs baseline: 3.5991x; 1.0439x over previous
#include <cuda_runtime.h>

// Integer-exact fused QAT conv stack (bit-exact vs fp32 reference).
// All-register design: each thread computes 8 output positions end-to-end.
// fq outputs are int8/128; convs via DP4A; requant = (+64)>>7 with sat-pack.

#define NT 256   // threads per block
#define PP 8     // output positions per thread

__device__ __forceinline__ int cvtrd(float v) {
    // floor(v*128 + 0.5): v*128 is exact (pow2), so fused fma == reference
    return __float2int_rd(fmaf(v, 128.0f, 0.5f));
}
__device__ __forceinline__ int packsat2(int a, int b, int c) {
    int d;
    asm("cvt.pack.sat.s8.s32.b32 %0, %1, %2, %3;"
        : "=r"(d) : "r"(a), "r"(b), "r"(c));
    return d;
}
// bytes [v0,v1,v2,v3]; same helper for weights and data -> dp4a order-invariant
__device__ __forceinline__ int pack4sat(int v0, int v1, int v2, int v3) {
    return packsat2(v1, v0, packsat2(v3, v2, 0));
}
__device__ __forceinline__ int qpack(float a, float b, float c, float d) {
    return pack4sat(cvtrd(a), cvtrd(b), cvtrd(c), cvtrd(d));
}

// wall layout: [0..23] w1 packed (oc*3+k), [24..31] 128*b1+64,
//              [32..43] w2 packed (oc*6+k*2+h), [44..45] 128*b2+64
template <bool GUARD>
__device__ __forceinline__ void tail_compute(
    const int* xw, const int* wall, int base, int L, float* ob)
{
    int yl[10], yh[10];
#pragma unroll
    for (int i = 0; i < 10; i++) {
        int x0 = xw[i], x1 = xw[i + 1], x2 = xw[i + 2];
        int yv[8];
#pragma unroll
        for (int oc = 0; oc < 8; oc++) {
            int acc = __dp4a(x0, wall[oc * 3 + 0], wall[24 + oc]);
            acc     = __dp4a(x1, wall[oc * 3 + 1], acc);
            acc     = __dp4a(x2, wall[oc * 3 + 2], acc);
            yv[oc]  = acc >> 7;
        }
        int lo = pack4sat(yv[0], yv[1], yv[2], yv[3]);
        int hi = pack4sat(yv[4], yv[5], yv[6], yv[7]);
        if (GUARD) {
            int q = base - 1 + i;
            bool valid = (q >= 0) && (q < L);
            lo = valid ? lo : 0;
            hi = valid ? hi : 0;
        }
        yl[i] = lo; yh[i] = hi;
    }

    float f0[PP], f1[PP];
#pragma unroll
    for (int p = 0; p < PP; p++) {
        int a0 = __dp4a(yl[p],     wall[32], wall[44]);
        a0     = __dp4a(yh[p],     wall[33], a0);
        a0     = __dp4a(yl[p + 1], wall[34], a0);
        a0     = __dp4a(yh[p + 1], wall[35], a0);
        a0     = __dp4a(yl[p + 2], wall[36], a0);
        a0     = __dp4a(yh[p + 2], wall[37], a0);
        int a1 = __dp4a(yl[p],     wall[38], wall[45]);
        a1     = __dp4a(yh[p],     wall[39], a1);
        a1     = __dp4a(yl[p + 1], wall[40], a1);
        a1     = __dp4a(yh[p + 1], wall[41], a1);
        a1     = __dp4a(yl[p + 2], wall[42], a1);
        a1     = __dp4a(yh[p + 2], wall[43], a1);
        f0[p] = (float)min(max(a0 >> 7, -128), 127) * 0.0078125f;
        f1[p] = (float)min(max(a1 >> 7, -128), 127) * 0.0078125f;
    }
    *(float4*)(ob + base)         = make_float4(f0[0], f0[1], f0[2], f0[3]);
    *(float4*)(ob + base + 4)     = make_float4(f0[4], f0[5], f0[6], f0[7]);
    *(float4*)(ob + (size_t)L + base)     = make_float4(f1[0], f1[1], f1[2], f1[3]);
    *(float4*)(ob + (size_t)L + base + 4) = make_float4(f1[4], f1[5], f1[6], f1[7]);
}

__global__ __launch_bounds__(NT) void fused_qconv_reg(
    const float* __restrict__ x,
    const float* __restrict__ w1, const float* __restrict__ b1,
    const float* __restrict__ gamma, const float* __restrict__ beta,
    const float* __restrict__ bn_mean, const float* __restrict__ bn_var,
    const float* __restrict__ w2, const float* __restrict__ b2,
    float* __restrict__ out, int L)
{
    __shared__ int wall[48];
    const int tid = threadIdx.x;

    // ---- weight prep (tiny, once per block) ----
    if (tid < 24) {
        int oc = tid / 3, k = tid % 3;
        float sf = (float)((double)gamma[oc] / sqrt((double)bn_var[oc] + 1e-5));
        const float* wb = w1 + oc * 12 + k;
        wall[tid] = qpack(wb[0] * sf, wb[3] * sf, wb[6] * sf, wb[9] * sf);
    } else if (tid < 32) {
        int oc = tid - 24;
        float sf = (float)((double)gamma[oc] / sqrt((double)bn_var[oc] + 1e-5));
        int bi = min(max(cvtrd((b1[oc] - bn_mean[oc]) * sf + beta[oc]), -128), 127);
        wall[tid] = bi * 128 + 64;
    } else if (tid < 44) {
        int t = tid - 32, oc = t / 6, r = t % 6, k = r >> 1, h = r & 1;
        const float* wb = w2 + oc * 24 + h * 12 + k;
        wall[tid] = qpack(wb[0], wb[3], wb[6], wb[9]);
    } else if (tid < 46) {
        wall[tid] = min(max(cvtrd(b2[tid - 44]), -128), 127) * 128 + 64;
    }
    __syncthreads();

    const int bb   = blockIdx.y;
    const int base = (blockIdx.x * NT + tid) * PP;   // first z position
    const float* xb = x + (size_t)bb * 4 * L;
    float* ob = out + (size_t)bb * 2 * L;

    int xw[12];   // packed fq(x), xw[j] = position base-2+j

    if (base >= 4 && base + 12 <= L) {
        // ---- fast path: 4 aligned float4 loads per channel ----
        const float* p0 = xb + (base - 4);
        const float* p1 = p0 + (size_t)L;
        const float* p2 = p0 + (size_t)2 * L;
        const float* p3 = p0 + (size_t)3 * L;

        float4 a0 = *(const float4*)(p0 +  0), a1 = *(const float4*)(p0 +  4);
        float4 a2 = *(const float4*)(p0 +  8), a3 = *(const float4*)(p0 + 12);
        float4 b0 = *(const float4*)(p1 +  0), b1v = *(const float4*)(p1 +  4);
        float4 b2v = *(const float4*)(p1 + 8), b3 = *(const float4*)(p1 + 12);
        float4 c0 = *(const float4*)(p2 +  0), c1 = *(const float4*)(p2 +  4);
        float4 c2 = *(const float4*)(p2 +  8), c3 = *(const float4*)(p2 + 12);
        float4 d0 = *(const float4*)(p3 +  0), d1 = *(const float4*)(p3 +  4);
        float4 d2 = *(const float4*)(p3 +  8), d3 = *(const float4*)(p3 + 12);

        xw[0]  = qpack(a0.z, b0.z,  c0.z, d0.z);
        xw[1]  = qpack(a0.w, b0.w,  c0.w, d0.w);
        xw[2]  = qpack(a1.x, b1v.x, c1.x, d1.x);
        xw[3]  = qpack(a1.y, b1v.y, c1.y, d1.y);
        xw[4]  = qpack(a1.z, b1v.z, c1.z, d1.z);
        xw[5]  = qpack(a1.w, b1v.w, c1.w, d1.w);
        xw[6]  = qpack(a2.x, b2v.x, c2.x, d2.x);
        xw[7]  = qpack(a2.y, b2v.y, c2.y, d2.y);
        xw[8]  = qpack(a2.z, b2v.z, c2.z, d2.z);
        xw[9]  = qpack(a2.w, b2v.w, c2.w, d2.w);
        xw[10] = qpack(a3.x, b3.x,  c3.x, d3.x);
        xw[11] = qpack(a3.y, b3.y,  c3.y, d3.y);

        tail_compute<false>(xw, wall, base, L, ob);
    } else {
        // ---- slow path: block-row edges only (2 threads per batch row) ----
#pragma unroll
        for (int j = 0; j < 12; j++) {
            int p = base - 2 + j, w = 0;
            if (p >= 0 && p < L)
                w = qpack(xb[p], xb[(size_t)L + p],
                          xb[(size_t)2 * L + p], xb[(size_t)3 * L + p]);
            xw[j] = w;
        }
        tail_compute<true>(xw, wall, base, L, ob);
    }
}

extern "C" void kernel_launch(void* const* d_in, const int* in_sizes, int n_in,
                              void* d_out, int out_size)
{
    const float* x       = (const float*)d_in[0];
    const float* w1      = (const float*)d_in[1];
    const float* b1      = (const float*)d_in[2];
    const float* gamma   = (const float*)d_in[3];
    const float* beta    = (const float*)d_in[4];
    const float* bn_mean = (const float*)d_in[5];
    const float* bn_var  = (const float*)d_in[6];
    const float* w2      = (const float*)d_in[7];
    const float* b2      = (const float*)d_in[8];
    float* out = (float*)d_out;

    const int B = 16;
    const int L = in_sizes[0] / (B * 4);

    dim3 grid(L / (NT * PP), B);
    fused_qconv_reg<<<grid, NT>>>(
        x, w1, b1, gamma, beta, bn_mean, bn_var, w2, b2, out, L);
}